// round 6
// baseline (speedup 1.0000x reference)
#include <cuda_runtime.h>
#include <cuda_bf16.h>

#define LGT   16
#define NROWS 4096
#define DCOLS 16000   // CLASSNUM * LGT

__device__ float        g_acc = 0.0f;
__device__ unsigned int g_cnt = 0u;

__global__ __launch_bounds__(256)
void rvsml_loss_kernel(const float* __restrict__ inputs,
                       const float* __restrict__ labels,
                       float* __restrict__ out) {
    const int row = blockIdx.x;
    const int tid = threadIdx.x;

    // NOTE: launched with 44KB of DYNAMIC shared memory (third launch param).
    // That reservation caps occupancy at 4 CTAs/SM (228KB carveout budget)
    // without any code the compiler could eliminate. 592 concurrent CTAs
    // instead of 1184 -> fewer interleaved HBM streams, shallower L1tex queues.
    __shared__ float warp_sums[8];
    __shared__ float sq_sh;

    // ---- Stream the row, accumulate sum of squares ----
    const float4* rowp = reinterpret_cast<const float4*>(inputs + (size_t)row * DCOLS);
    const int nvec = DCOLS / 4;  // 4000

    float acc = 0.0f;
    #pragma unroll 4
    for (int i = tid; i < nvec; i += 256) {
        float4 v = rowp[i];
        acc = fmaf(v.x, v.x, acc);
        acc = fmaf(v.y, v.y, acc);
        acc = fmaf(v.z, v.z, acc);
        acc = fmaf(v.w, v.w, acc);
    }

    // ---- Block reduce acc -> sq ----
    #pragma unroll
    for (int off = 16; off > 0; off >>= 1)
        acc += __shfl_xor_sync(0xFFFFFFFFu, acc, off);
    if ((tid & 31) == 0) warp_sums[tid >> 5] = acc;
    __syncthreads();

    if (tid < 32) {
        float v = (tid < 8) ? warp_sums[tid] : 0.0f;
        #pragma unroll
        for (int off = 4; off > 0; off >>= 1)
            v += __shfl_xor_sync(0xFFFFFFFFu, v, off);
        if (tid == 0) sq_sh = v;
    }
    __syncthreads();

    // ---- Gather + weighted contribution (warp 0; row is L2-resident) ----
    if (tid < 32) {
        const float sq = sq_sh;
        const float* lab = labels + row * (LGT + 1);
        float contrib = 0.0f;
        if (tid < LGT) {
            const int c = (int)lab[LGT];
            const float w = lab[tid];
            const float g = inputs[(size_t)row * DCOLS + c * LGT + tid];
            contrib = w * (sq + 1.0f - 2.0f * g);
        }
        #pragma unroll
        for (int off = 16; off > 0; off >>= 1)
            contrib += __shfl_xor_sync(0xFFFFFFFFu, contrib, off);

        if (tid == 0) {
            atomicAdd(&g_acc, contrib);
            __threadfence();
            const unsigned ticket = atomicAdd(&g_cnt, 1u);
            if (ticket == NROWS - 1) {
                // All contributions visible (each CTA fenced before its
                // counter increment). Read + reset for the next graph replay.
                const float total = atomicExch(&g_acc, 0.0f);
                out[0] = total * (1.0f / (float)NROWS);
                g_cnt = 0u;
                __threadfence();
            }
        }
    }
}

extern "C" void kernel_launch(void* const* d_in, const int* in_sizes, int n_in,
                              void* d_out, int out_size) {
    const float* inputs = (const float*)d_in[0];
    const float* labels = (const float*)d_in[1];
    float* out = (float*)d_out;

    // 44KB dynamic smem: occupancy limiter (see kernel comment).
    rvsml_loss_kernel<<<NROWS, 256, 44 * 1024>>>(inputs, labels, out);
}

// round 7
// speedup vs baseline: 1.2447x; 1.2447x over previous
#include <cuda_runtime.h>
#include <cuda_bf16.h>

#define LGT      16
#define NROWS    4096
#define DCOLS    16000          // CLASSNUM * LGT
#define NWORKERS (152 * 8)      // GB300: 152 SMs, 8 CTAs/SM resident

__device__ float        g_acc  = 0.0f;
__device__ unsigned int g_cnt  = 0u;
__device__ unsigned int g_task = 0u;

__global__ __launch_bounds__(256, 8)
void rvsml_loss_kernel(const float* __restrict__ inputs,
                       const float* __restrict__ labels,
                       float* __restrict__ out) {
    const int tid = threadIdx.x;

    __shared__ float    warp_sums[8];
    __shared__ unsigned next_sh;

    // First ticket
    if (tid == 0) next_sh = atomicAdd(&g_task, 1u);
    __syncthreads();
    unsigned row = next_sh;

    float cta_total = 0.0f;  // meaningful in tid 0 only

    while (row < NROWS) {
        // ---- Stream the row, accumulate sum of squares ----
        const float4* rowp =
            reinterpret_cast<const float4*>(inputs + (size_t)row * DCOLS);
        float acc = 0.0f;
        #pragma unroll 4
        for (int i = tid; i < DCOLS / 4; i += 256) {
            float4 v = rowp[i];
            acc = fmaf(v.x, v.x, acc);
            acc = fmaf(v.y, v.y, acc);
            acc = fmaf(v.z, v.z, acc);
            acc = fmaf(v.w, v.w, acc);
        }

        // Prefetch next ticket now; ~320cyc ATOMG latency hides under the
        // block reduce + gather below.
        if (tid == 0) next_sh = atomicAdd(&g_task, 1u);

        // ---- Block reduce acc -> sq (warp 0 holds result) ----
        #pragma unroll
        for (int off = 16; off > 0; off >>= 1)
            acc += __shfl_xor_sync(0xFFFFFFFFu, acc, off);
        if ((tid & 31) == 0) warp_sums[tid >> 5] = acc;
        __syncthreads();

        if (tid < 32) {
            float v = (tid < 8) ? warp_sums[tid] : 0.0f;
            #pragma unroll
            for (int off = 4; off > 0; off >>= 1)
                v += __shfl_xor_sync(0xFFFFFFFFu, v, off);
            const float sq = __shfl_sync(0xFFFFFFFFu, v, 0);

            // ---- Gather + weighted contribution (row is L2-resident) ----
            const float* lab = labels + row * (LGT + 1);
            float contrib = 0.0f;
            if (tid < LGT) {
                const int   c = (int)lab[LGT];
                const float w = lab[tid];
                const float g = inputs[(size_t)row * DCOLS + c * LGT + tid];
                contrib = w * (sq + 1.0f - 2.0f * g);
            }
            #pragma unroll
            for (int off = 16; off > 0; off >>= 1)
                contrib += __shfl_xor_sync(0xFFFFFFFFu, contrib, off);
            if (tid == 0) cta_total += contrib;
        }

        const unsigned nrow = next_sh;   // all threads read between barriers
        __syncthreads();                 // protects next_sh + warp_sums reuse
        row = nrow;
    }

    // ---- One global atomic per CTA; last CTA finalizes + resets ----
    if (tid == 0) {
        atomicAdd(&g_acc, cta_total);
        __threadfence();
        const unsigned done = atomicAdd(&g_cnt, 1u);
        if (done == NWORKERS - 1) {
            // All contributions visible (each CTA fenced before its
            // counter increment). Read + reset for the next graph replay.
            const float total = atomicExch(&g_acc, 0.0f);
            out[0] = total * (1.0f / (float)NROWS);
            g_cnt  = 0u;
            g_task = 0u;
            __threadfence();
        }
    }
}

extern "C" void kernel_launch(void* const* d_in, const int* in_sizes, int n_in,
                              void* d_out, int out_size) {
    const float* inputs = (const float*)d_in[0];
    const float* labels = (const float*)d_in[1];
    float* out = (float*)d_out;

    rvsml_loss_kernel<<<NWORKERS, 256>>>(inputs, labels, out);
}